// round 16
// baseline (speedup 1.0000x reference)
#include <cuda_runtime.h>
#include <cstdint>

#define BB 4
#define TT 1024
#define DEMB 1024
#define NH 16
#define DH 64
#define LL 1344
#define BH 64          // BB*NH

#define BM 128
#define BN 64
#define BKF 32         // proj K floats per chunk
#define ASTR 36        // proj smem stride
#define FSTR 68        // fused kernel smem stride (64 + 4)

// Scratch (static __device__ globals; no runtime allocation).
__device__ float    g_K [(size_t)BH * TT * DH];         // [b,h,t,d]  (tf32-rounded)
__device__ float    g_Vt[(size_t)BH * DH * TT];         // [b,h,d,t]  (tf32-rounded)
__device__ uint32_t g_Mp[(size_t)BB * LL * (TT / 32)];  // packed mask bits

// proj smem layout (floats)
#define A_OFF0 0
#define B_OFF0 (BM * ASTR)
#define A_OFF1 (B_OFF0 + BN * ASTR)
#define B_OFF1 (A_OFF1 + BM * ASTR)
#define BIAS_OFF (B_OFF1 + BN * ASTR)
#define SMEMF (BIAS_OFF + 64)
#define SMEMB (SMEMF * 4)

// fused smem layout (floats): lq + 2x(K,V) buffers + P + rsum
#define LQ_OFF   0
#define TBUF_SZ  (64 * FSTR)                    // 4352
#define KS_OFF   (BM * FSTR)                    // 8704   (K buf0, K buf1)
#define VS_OFF   (KS_OFF + 2 * TBUF_SZ)         // 17408  (V buf0, V buf1)
#define PS_OFF   (VS_OFF + 2 * TBUF_SZ)         // 26112
#define RSUM_OFF (PS_OFF + BM * FSTR)           // 34816
#define SMEM_ATT_B ((RSUM_OFF + 256) * 4)       // ~140 KB

static __device__ __forceinline__ float f2tf(float f) {
    uint32_t r; asm("cvt.rna.tf32.f32 %0, %1;" : "=r"(r) : "f"(f));
    return __uint_as_float(r);
}

static __device__ __forceinline__ uint32_t smem_u32(const void* p) {
    uint32_t a;
    asm("{ .reg .u64 t; cvta.to.shared.u64 t, %1; cvt.u32.u64 %0, t; }" : "=r"(a) : "l"(p));
    return a;
}

static __device__ __forceinline__ void cpa16(uint32_t dst, const float* src) {
    asm volatile("cp.async.cg.shared.global [%0], [%1], 16;" :: "r"(dst), "l"(src));
}

static __device__ __forceinline__ void mma8(float* c, const uint32_t* a, const uint32_t* b) {
    asm volatile("mma.sync.aligned.m16n8k8.row.col.f32.tf32.tf32.f32 "
                 "{%0,%1,%2,%3}, {%4,%5,%6,%7}, {%8,%9}, {%0,%1,%2,%3};"
                 : "+f"(c[0]), "+f"(c[1]), "+f"(c[2]), "+f"(c[3])
                 : "r"(a[0]), "r"(a[1]), "r"(a[2]), "r"(a[3]), "r"(b[0]), "r"(b[1]));
}

template<int STR, int KSTEPS>
static __device__ __forceinline__ void compute_mma(const float* __restrict__ As,
                                                   const float* __restrict__ Bs,
                                                   float c[2][4][4],
                                                   int wm, int wn, int g, int tig)
{
    #pragma unroll
    for (int ks = 0; ks < KSTEPS; ks++) {
        const int kb = ks * 8;
        uint32_t a[2][4], b[4][2];
        #pragma unroll
        for (int i = 0; i < 2; i++) {
            const float* p = As + (wm * 32 + i * 16 + g) * STR + kb + tig;
            a[i][0] = __float_as_uint(p[0]);
            a[i][1] = __float_as_uint(p[8 * STR]);
            a[i][2] = __float_as_uint(p[4]);
            a[i][3] = __float_as_uint(p[8 * STR + 4]);
        }
        #pragma unroll
        for (int j = 0; j < 4; j++) {
            const float* p = Bs + (wn * 32 + j * 8 + g) * STR + kb + tig;
            b[j][0] = __float_as_uint(p[0]);
            b[j][1] = __float_as_uint(p[4]);
        }
        #pragma unroll
        for (int i = 0; i < 2; i++)
            #pragma unroll
            for (int j = 0; j < 4; j++)
                mma8(c[i][j], a[i], b[j]);
    }
}

static __device__ __forceinline__ void sts_chunk(float* __restrict__ sm, int aoff, int boff,
                                                 const float4* pa, const float4* pb, int tid)
{
    #pragma unroll
    for (int jj = 0; jj < 4; jj++) {
        const int idx = tid + jj * 256;
        const int row = idx >> 3, f4 = idx & 7;
        float* d = sm + aoff + row * ASTR + f4 * 4;
        d[0] = f2tf(pa[jj].x); d[1] = f2tf(pa[jj].y);
        d[2] = f2tf(pa[jj].z); d[3] = f2tf(pa[jj].w);
    }
    #pragma unroll
    for (int jj = 0; jj < 2; jj++) {
        const int idx = tid + jj * 256;
        const int row = idx >> 3, f4 = idx & 7;
        float* d = sm + boff + row * ASTR + f4 * 4;
        d[0] = f2tf(pb[jj].x); d[1] = f2tf(pb[jj].y);
        d[2] = f2tf(pb[jj].z); d[3] = f2tf(pb[jj].w);
    }
}

// ---------------------------------------------------------------------------
// Mask pack: int32 [b,l,t] -> bit per t.  One warp per (b,l) row.
// ---------------------------------------------------------------------------
__global__ __launch_bounds__(256)
void pack_mask(const int* __restrict__ mask)
{
    const int row = blockIdx.x * 8 + (threadIdx.x >> 5);
    const int lane = threadIdx.x & 31;
    const int* __restrict__ M = mask + (size_t)row * TT;
    uint32_t myword = 0;
    #pragma unroll
    for (int w = 0; w < 32; w++) {
        uint32_t bal = __ballot_sync(0xffffffffu, M[w * 32 + lane] != 0);
        if (lane == w) myword = bal;
    }
    g_Mp[(size_t)row * 32 + lane] = myword;
}

// ---------------------------------------------------------------------------
// GEMM 1: projections. C[4096 x 1024] = X @ W^T (+bias). z=0 -> K, z=1 -> V^T.
// (R6-exact version.)
// ---------------------------------------------------------------------------
__global__ __launch_bounds__(256)
void proj_kernel(const float* __restrict__ x,
                 const float* __restrict__ wk, const float* __restrict__ bk,
                 const float* __restrict__ wv, const float* __restrict__ bv)
{
    extern __shared__ float sm[];
    const int which = blockIdx.z;
    const float* __restrict__ w    = which ? wv : wk;
    const float* __restrict__ bias = which ? bv : bk;

    const int m0 = blockIdx.x * BM;
    const int n0 = blockIdx.y * BN;
    const int tid = threadIdx.x;
    const int warp = tid >> 5, lane = tid & 31;
    const int wm = warp >> 1, wn = warp & 1;
    const int g = lane >> 2, tig = lane & 3;

    if (tid < 64) sm[BIAS_OFF + tid] = bias[n0 + tid];

    float c[2][4][4] = {};
    float4 pa[4], pb[2];
    const int NC = DEMB / BKF;  // 32

    #pragma unroll
    for (int jj = 0; jj < 4; jj++) {
        const int idx = tid + jj * 256, row = idx >> 3, f4 = idx & 7;
        pa[jj] = *(const float4*)&x[(size_t)(m0 + row) * DEMB + f4 * 4];
    }
    #pragma unroll
    for (int jj = 0; jj < 2; jj++) {
        const int idx = tid + jj * 256, row = idx >> 3, f4 = idx & 7;
        pb[jj] = *(const float4*)&w[(size_t)(n0 + row) * DEMB + f4 * 4];
    }
    sts_chunk(sm, A_OFF0, B_OFF0, pa, pb, tid);
    __syncthreads();

    for (int cc = 0; cc < NC; cc++) {
        const int cur = cc & 1;
        if (cc + 1 < NC) {
            const int kofs = (cc + 1) * BKF;
            #pragma unroll
            for (int jj = 0; jj < 4; jj++) {
                const int idx = tid + jj * 256, row = idx >> 3, f4 = idx & 7;
                pa[jj] = *(const float4*)&x[(size_t)(m0 + row) * DEMB + kofs + f4 * 4];
            }
            #pragma unroll
            for (int jj = 0; jj < 2; jj++) {
                const int idx = tid + jj * 256, row = idx >> 3, f4 = idx & 7;
                pb[jj] = *(const float4*)&w[(size_t)(n0 + row) * DEMB + kofs + f4 * 4];
            }
        }
        compute_mma<ASTR, 4>(sm + (cur ? A_OFF1 : A_OFF0), sm + (cur ? B_OFF1 : B_OFF0),
                             c, wm, wn, g, tig);
        if (cc + 1 < NC)
            sts_chunk(sm, cur ? A_OFF0 : A_OFF1, cur ? B_OFF0 : B_OFF1, pa, pb, tid);
        __syncthreads();
    }

    const int b_ = m0 >> 10;
    const int h  = blockIdx.y;
    #pragma unroll
    for (int i = 0; i < 2; i++) {
        const int m1 = m0 + wm * 32 + i * 16 + g;
        const int t1 = m1 & 1023, t2 = (m1 + 8) & 1023;
        #pragma unroll
        for (int j = 0; j < 4; j++) {
            const int nl = wn * 32 + j * 8 + tig * 2;
            const float bz0 = sm[BIAS_OFF + nl], bz1 = sm[BIAS_OFF + nl + 1];
            if (which == 0) {
                float* d0 = g_K + (((size_t)(b_ * NH + h) * TT + t1) * DH) + nl;
                float* d1 = g_K + (((size_t)(b_ * NH + h) * TT + t2) * DH) + nl;
                float2 v0 = { f2tf(c[i][j][0] + bz0), f2tf(c[i][j][1] + bz1) };
                float2 v1 = { f2tf(c[i][j][2] + bz0), f2tf(c[i][j][3] + bz1) };
                *(float2*)d0 = v0;
                *(float2*)d1 = v1;
            } else {
                float* base = g_Vt + ((size_t)(b_ * NH + h) * DH) * TT;
                base[(size_t)nl * TT + t1]       = f2tf(c[i][j][0] + bz0);
                base[(size_t)(nl + 1) * TT + t1] = f2tf(c[i][j][1] + bz1);
                base[(size_t)nl * TT + t2]       = f2tf(c[i][j][2] + bz0);
                base[(size_t)(nl + 1) * TT + t2] = f2tf(c[i][j][3] + bz1);
            }
        }
    }
}

// ---------------------------------------------------------------------------
// Fused attention: R6 structure EXACTLY (3 block barriers per tile), with ONE
// change: double-buffered K/V so the next tile's fetch overlaps this tile's
// compute. Race-free: prefetch into buf^1 is issued after the trailing
// __syncthreads of the iteration that last read buf^1.
// grid (11, 64): x = l-tile (128, guarded at 1344), y = b*16+h.
// ---------------------------------------------------------------------------
__global__ __launch_bounds__(256)
void attn_fused(const float* __restrict__ latq, float* __restrict__ out)
{
    extern __shared__ float sm[];
    float* lq_s = sm + LQ_OFF;
    float* Ps   = sm + PS_OFF;
    float* rsum = sm + RSUM_OFF;

    const int m0 = blockIdx.x * BM;
    const int bz = blockIdx.y;
    const int b  = bz >> 4, h = bz & 15;
    const int tid = threadIdx.x;
    const int warp = tid >> 5, lane = tid & 31;
    const int wm = warp >> 1, wn = warp & 1;
    const int g = lane >> 2, tig = lane & 3;

    const float* __restrict__ A  = latq + (size_t)h * (LL * DH);
    const float* __restrict__ Kg = g_K  + (size_t)bz * TT * DH;
    const float* __restrict__ Vg = g_Vt + (size_t)bz * DH * TT;
    const uint32_t* __restrict__ Mp = g_Mp + (size_t)b * LL * 32;

    const uint32_t smb = smem_u32(sm);

    // cp.async staging of one K/V tile into buffer bi
    auto stage = [&](int tile, int bi) {
        const int t0 = tile * 64;
        const uint32_t kb = smb + (uint32_t)(KS_OFF + bi * TBUF_SZ) * 4u;
        const uint32_t vb = smb + (uint32_t)(VS_OFF + bi * TBUF_SZ) * 4u;
        #pragma unroll
        for (int jj = 0; jj < 4; jj++) {
            const int idx = tid + jj * 256;
            const int row = idx >> 4, f4 = idx & 15;
            const uint32_t doff = (uint32_t)(row * FSTR + f4 * 4) * 4u;
            cpa16(kb + doff, Kg + (size_t)(t0 + row) * DH + f4 * 4);
            cpa16(vb + doff, Vg + (size_t)row * TT + t0 + f4 * 4);
        }
        asm volatile("cp.async.commit_group;");
    };

    // fetch tile 0 first so it overlaps the lq staging work below
    stage(0, 0);

    // stage lq (x0.25, tf32)
    #pragma unroll
    for (int jj = 0; jj < 8; jj++) {
        const int idx = tid + jj * 256;
        const int row = idx >> 4, f4 = idx & 15;
        float4 v = {0.f, 0.f, 0.f, 0.f};
        if (m0 + row < LL) {
            v = *(const float4*)&A[(size_t)(m0 + row) * DH + f4 * 4];
            v.x *= 0.25f; v.y *= 0.25f; v.z *= 0.25f; v.w *= 0.25f;
        }
        float* d = lq_s + row * FSTR + f4 * 4;
        d[0] = f2tf(v.x); d[1] = f2tf(v.y); d[2] = f2tf(v.z); d[3] = f2tf(v.w);
    }

    float co[2][4][4] = {};
    float srow[2][2] = {};

    for (int tile = 0; tile < TT / 64; tile++) {
        const int buf = tile & 1;
        // Prefetch next tile into buf^1 (safe: buf^1 reads finished before the
        // trailing __syncthreads of the previous iteration), then wait current.
        if (tile + 1 < TT / 64) {
            stage(tile + 1, buf ^ 1);
            asm volatile("cp.async.wait_group 1;" ::: "memory");
        } else {
            asm volatile("cp.async.wait_group 0;" ::: "memory");
        }
        __syncthreads();   // staging (and lq on tile 0) visible block-wide

        const float* Ks = sm + KS_OFF + buf * TBUF_SZ;
        const float* Vs = sm + VS_OFF + buf * TBUF_SZ;

        // S = lq @ K^T
        float cs[2][4][4] = {};
        compute_mma<FSTR, 8>(lq_s, Ks, cs, wm, wn, g, tig);

        // mask words
        uint32_t mw[2][2];
        #pragma unroll
        for (int i = 0; i < 2; i++) {
            const int lA = m0 + wm * 32 + i * 16 + g;
            const int lB = lA + 8;
            mw[i][0] = (lA < LL) ? Mp[(size_t)lA * 32 + tile * 2 + wn] : 0u;
            mw[i][1] = (lB < LL) ? Mp[(size_t)lB * 32 + tile * 2 + wn] : 0u;
        }

        // p = mask ? exp(s) : 0 ; accumulate register row sums ; write P
        #pragma unroll
        for (int i = 0; i < 2; i++) {
            #pragma unroll
            for (int half = 0; half < 2; half++) {
                const int r = wm * 32 + i * 16 + g + half * 8;
                const uint32_t w32 = mw[i][half];
                const int k = half * 2;
                float sl = 0.f;
                #pragma unroll
                for (int j = 0; j < 4; j++) {
                    const int b0 = j * 8 + tig * 2;
                    const float p0 = ((w32 >> b0) & 1)       ? __expf(cs[i][j][k])     : 0.f;
                    const float p1 = ((w32 >> (b0 + 1)) & 1) ? __expf(cs[i][j][k + 1]) : 0.f;
                    sl += p0 + p1;
                    float2 pv = { f2tf(p0), f2tf(p1) };
                    *(float2*)(Ps + r * FSTR + wn * 32 + b0) = pv;
                }
                srow[i][half] += sl;
            }
        }
        __syncthreads();   // P visible block-wide (R6-style block barrier)

        // O += P @ V
        compute_mma<FSTR, 8>(Ps, Vs, co, wm, wn, g, tig);
        __syncthreads();   // trailing: orders K/V + P reads before next
                           // iteration's prefetch into buf^1 / P rewrite.
    }

    // final row-sum reduction: tig shfl, then combine the two wn halves via smem
    #pragma unroll
    for (int i = 0; i < 2; i++) {
        #pragma unroll
        for (int half = 0; half < 2; half++) {
            const int r = wm * 32 + i * 16 + g + half * 8;
            float s = srow[i][half];
            s += __shfl_xor_sync(0xffffffffu, s, 1);
            s += __shfl_xor_sync(0xffffffffu, s, 2);
            if (tig == 0) rsum[r * 2 + wn] = s;
        }
    }
    __syncthreads();

    // epilogue: out[b, l, h*64 + d] = O / rowsum  (0 if fully masked)
    #pragma unroll
    for (int i = 0; i < 2; i++) {
        const int rA = wm * 32 + i * 16 + g, rB = rA + 8;
        const int lA = m0 + rA, lB = m0 + rB;
        const float dA = rsum[rA * 2] + rsum[rA * 2 + 1];
        const float dB = rsum[rB * 2] + rsum[rB * 2 + 1];
        const float invA = dA > 0.f ? __frcp_rn(dA) : 0.f;
        const float invB = dB > 0.f ? __frcp_rn(dB) : 0.f;
        #pragma unroll
        for (int j = 0; j < 4; j++) {
            const int nl = wn * 32 + j * 8 + tig * 2;
            if (lA < LL) {
                float2 v0 = { co[i][j][0] * invA, co[i][j][1] * invA };
                *(float2*)(out + ((size_t)b * LL + lA) * DEMB + h * DH + nl) = v0;
            }
            if (lB < LL) {
                float2 v1 = { co[i][j][2] * invB, co[i][j][3] * invB };
                *(float2*)(out + ((size_t)b * LL + lB) * DEMB + h * DH + nl) = v1;
            }
        }
    }
}

// ---------------------------------------------------------------------------
extern "C" void kernel_launch(void* const* d_in, const int* in_sizes, int n_in,
                              void* d_out, int out_size)
{
    const float* x    = (const float*)d_in[0];
    const int*   msk  = (const int*)d_in[1];
    const float* latq = (const float*)d_in[2];
    const float* wk   = (const float*)d_in[3];
    const float* bk   = (const float*)d_in[4];
    const float* wv   = (const float*)d_in[5];
    const float* bv   = (const float*)d_in[6];
    float*       out  = (float*)d_out;

    cudaFuncSetAttribute(proj_kernel, cudaFuncAttributeMaxDynamicSharedMemorySize, SMEMB);
    cudaFuncSetAttribute(attn_fused,  cudaFuncAttributeMaxDynamicSharedMemorySize, SMEM_ATT_B);

    pack_mask<<<BB * LL / 8, 256>>>(msk);
    proj_kernel<<<dim3(32, 16, 2), 256, SMEMB>>>(x, wk, bk, wv, bv);
    attn_fused <<<dim3(11, 64),    256, SMEM_ATT_B>>>(latq, out);
}

// round 17
// speedup vs baseline: 1.0621x; 1.0621x over previous
#include <cuda_runtime.h>
#include <cstdint>

#define BB 4
#define TT 1024
#define DEMB 1024
#define NH 16
#define DH 64
#define LL 1344
#define BH 64          // BB*NH

#define BM 128
#define BN 64
#define BKF 32         // proj K floats per chunk
#define ASTR 36        // proj smem stride
#define FSTR 68        // fused kernel smem stride (64 + 4)

// Scratch (static __device__ globals; no runtime allocation).
__device__ float    g_K [(size_t)BH * TT * DH];   // [b,h,t,d]  (tf32-rounded)
__device__ float    g_Vt[(size_t)BH * DH * TT];   // [b,h,d,t]  (tf32-rounded)
__device__ uint32_t g_Mp[(size_t)BB * LL * (TT / 32)];  // packed mask bits

// proj smem layout (floats)
#define A_OFF0 0
#define B_OFF0 (BM * ASTR)
#define A_OFF1 (B_OFF0 + BN * ASTR)
#define B_OFF1 (A_OFF1 + BM * ASTR)
#define BIAS_OFF (B_OFF1 + BN * ASTR)
#define SMEMF (BIAS_OFF + 64)
#define SMEMB (SMEMF * 4)

// fused smem layout (floats)
#define LQ_OFF  0
#define KS_OFF  (BM * FSTR)                 // 8704
#define VS_OFF  (KS_OFF + 64 * FSTR)        // 13056
#define PS_OFF  (VS_OFF + 64 * FSTR)        // 17408
#define RSUM_OFF (PS_OFF + BM * FSTR)       // 26112
#define SMEM_ATT_B ((RSUM_OFF + 256) * 4)   // ~105 KB

static __device__ __forceinline__ float f2tf(float f) {
    uint32_t r; asm("cvt.rna.tf32.f32 %0, %1;" : "=r"(r) : "f"(f));
    return __uint_as_float(r);
}

static __device__ __forceinline__ uint32_t smem_u32(const void* p) {
    uint32_t a;
    asm("{ .reg .u64 t; cvta.to.shared.u64 t, %1; cvt.u32.u64 %0, t; }" : "=r"(a) : "l"(p));
    return a;
}

static __device__ __forceinline__ void cpa16(uint32_t dst, const float* src) {
    asm volatile("cp.async.cg.shared.global [%0], [%1], 16;" :: "r"(dst), "l"(src));
}

static __device__ __forceinline__ void mma8(float* c, const uint32_t* a, const uint32_t* b) {
    asm volatile("mma.sync.aligned.m16n8k8.row.col.f32.tf32.tf32.f32 "
                 "{%0,%1,%2,%3}, {%4,%5,%6,%7}, {%8,%9}, {%0,%1,%2,%3};"
                 : "+f"(c[0]), "+f"(c[1]), "+f"(c[2]), "+f"(c[3])
                 : "r"(a[0]), "r"(a[1]), "r"(a[2]), "r"(a[3]), "r"(b[0]), "r"(b[1]));
}

template<int STR, int KSTEPS>
static __device__ __forceinline__ void compute_mma(const float* __restrict__ As,
                                                   const float* __restrict__ Bs,
                                                   float c[2][4][4],
                                                   int wm, int wn, int g, int tig)
{
    #pragma unroll
    for (int ks = 0; ks < KSTEPS; ks++) {
        const int kb = ks * 8;
        uint32_t a[2][4], b[4][2];
        #pragma unroll
        for (int i = 0; i < 2; i++) {
            const float* p = As + (wm * 32 + i * 16 + g) * STR + kb + tig;
            a[i][0] = __float_as_uint(p[0]);
            a[i][1] = __float_as_uint(p[8 * STR]);
            a[i][2] = __float_as_uint(p[4]);
            a[i][3] = __float_as_uint(p[8 * STR + 4]);
        }
        #pragma unroll
        for (int j = 0; j < 4; j++) {
            const float* p = Bs + (wn * 32 + j * 8 + g) * STR + kb + tig;
            b[j][0] = __float_as_uint(p[0]);
            b[j][1] = __float_as_uint(p[4]);
        }
        #pragma unroll
        for (int i = 0; i < 2; i++)
            #pragma unroll
            for (int j = 0; j < 4; j++)
                mma8(c[i][j], a[i], b[j]);
    }
}

static __device__ __forceinline__ void sts_chunk(float* __restrict__ sm, int aoff, int boff,
                                                 const float4* pa, const float4* pb, int tid)
{
    #pragma unroll
    for (int jj = 0; jj < 4; jj++) {
        const int idx = tid + jj * 256;
        const int row = idx >> 3, f4 = idx & 7;
        float* d = sm + aoff + row * ASTR + f4 * 4;
        d[0] = f2tf(pa[jj].x); d[1] = f2tf(pa[jj].y);
        d[2] = f2tf(pa[jj].z); d[3] = f2tf(pa[jj].w);
    }
    #pragma unroll
    for (int jj = 0; jj < 2; jj++) {
        const int idx = tid + jj * 256;
        const int row = idx >> 3, f4 = idx & 7;
        float* d = sm + boff + row * ASTR + f4 * 4;
        d[0] = f2tf(pb[jj].x); d[1] = f2tf(pb[jj].y);
        d[2] = f2tf(pb[jj].z); d[3] = f2tf(pb[jj].w);
    }
}

// ---------------------------------------------------------------------------
// Mask pack: int32 [b,l,t] -> bit per t.  One warp per (b,l) row.
// ---------------------------------------------------------------------------
__global__ __launch_bounds__(256)
void pack_mask(const int* __restrict__ mask)
{
    const int row = blockIdx.x * 8 + (threadIdx.x >> 5);
    const int lane = threadIdx.x & 31;
    const int* __restrict__ M = mask + (size_t)row * TT;
    uint32_t myword = 0;
    #pragma unroll
    for (int w = 0; w < 32; w++) {
        uint32_t bal = __ballot_sync(0xffffffffu, M[w * 32 + lane] != 0);
        if (lane == w) myword = bal;
    }
    g_Mp[(size_t)row * 32 + lane] = myword;
}

// ---------------------------------------------------------------------------
// GEMM 1: projections. C[4096 x 1024] = X @ W^T (+bias). z=0 -> K, z=1 -> V^T.
// Results stored tf32-rounded (identical to what the attn mma would consume).
// ---------------------------------------------------------------------------
__global__ __launch_bounds__(256)
void proj_kernel(const float* __restrict__ x,
                 const float* __restrict__ wk, const float* __restrict__ bk,
                 const float* __restrict__ wv, const float* __restrict__ bv)
{
    extern __shared__ float sm[];
    const int which = blockIdx.z;
    const float* __restrict__ w    = which ? wv : wk;
    const float* __restrict__ bias = which ? bv : bk;

    const int m0 = blockIdx.x * BM;
    const int n0 = blockIdx.y * BN;
    const int tid = threadIdx.x;
    const int warp = tid >> 5, lane = tid & 31;
    const int wm = warp >> 1, wn = warp & 1;
    const int g = lane >> 2, tig = lane & 3;

    if (tid < 64) sm[BIAS_OFF + tid] = bias[n0 + tid];

    float c[2][4][4] = {};
    float4 pa[4], pb[2];
    const int NC = DEMB / BKF;  // 32

    #pragma unroll
    for (int jj = 0; jj < 4; jj++) {
        const int idx = tid + jj * 256, row = idx >> 3, f4 = idx & 7;
        pa[jj] = *(const float4*)&x[(size_t)(m0 + row) * DEMB + f4 * 4];
    }
    #pragma unroll
    for (int jj = 0; jj < 2; jj++) {
        const int idx = tid + jj * 256, row = idx >> 3, f4 = idx & 7;
        pb[jj] = *(const float4*)&w[(size_t)(n0 + row) * DEMB + f4 * 4];
    }
    sts_chunk(sm, A_OFF0, B_OFF0, pa, pb, tid);
    __syncthreads();

    for (int cc = 0; cc < NC; cc++) {
        const int cur = cc & 1;
        if (cc + 1 < NC) {
            const int kofs = (cc + 1) * BKF;
            #pragma unroll
            for (int jj = 0; jj < 4; jj++) {
                const int idx = tid + jj * 256, row = idx >> 3, f4 = idx & 7;
                pa[jj] = *(const float4*)&x[(size_t)(m0 + row) * DEMB + kofs + f4 * 4];
            }
            #pragma unroll
            for (int jj = 0; jj < 2; jj++) {
                const int idx = tid + jj * 256, row = idx >> 3, f4 = idx & 7;
                pb[jj] = *(const float4*)&w[(size_t)(n0 + row) * DEMB + kofs + f4 * 4];
            }
        }
        compute_mma<ASTR, 4>(sm + (cur ? A_OFF1 : A_OFF0), sm + (cur ? B_OFF1 : B_OFF0),
                             c, wm, wn, g, tig);
        if (cc + 1 < NC)
            sts_chunk(sm, cur ? A_OFF0 : A_OFF1, cur ? B_OFF0 : B_OFF1, pa, pb, tid);
        __syncthreads();
    }

    const int b_ = m0 >> 10;
    const int h  = blockIdx.y;
    #pragma unroll
    for (int i = 0; i < 2; i++) {
        const int m1 = m0 + wm * 32 + i * 16 + g;
        const int t1 = m1 & 1023, t2 = (m1 + 8) & 1023;
        #pragma unroll
        for (int j = 0; j < 4; j++) {
            const int nl = wn * 32 + j * 8 + tig * 2;
            const float bz0 = sm[BIAS_OFF + nl], bz1 = sm[BIAS_OFF + nl + 1];
            if (which == 0) {
                float* d0 = g_K + (((size_t)(b_ * NH + h) * TT + t1) * DH) + nl;
                float* d1 = g_K + (((size_t)(b_ * NH + h) * TT + t2) * DH) + nl;
                float2 v0 = { f2tf(c[i][j][0] + bz0), f2tf(c[i][j][1] + bz1) };
                float2 v1 = { f2tf(c[i][j][2] + bz0), f2tf(c[i][j][3] + bz1) };
                *(float2*)d0 = v0;
                *(float2*)d1 = v1;
            } else {
                float* base = g_Vt + ((size_t)(b_ * NH + h) * DH) * TT;
                base[(size_t)nl * TT + t1]       = f2tf(c[i][j][0] + bz0);
                base[(size_t)(nl + 1) * TT + t1] = f2tf(c[i][j][1] + bz1);
                base[(size_t)nl * TT + t2]       = f2tf(c[i][j][2] + bz0);
                base[(size_t)(nl + 1) * TT + t2] = f2tf(c[i][j][3] + bz1);
            }
        }
    }
}

// ---------------------------------------------------------------------------
// Fused attention: S = lq@K^T, p = mask ? exp(s) : 0 (no max shift — scores
// are bounded small, softmax is shift-invariant), O = p@V, out = O / rowsum.
// grid (11, 64): x = l-tile (128, guarded at 1344), y = b*16+h.
// ---------------------------------------------------------------------------
__global__ __launch_bounds__(256)
void attn_fused(const float* __restrict__ latq, float* __restrict__ out)
{
    extern __shared__ float sm[];
    float* lq_s = sm + LQ_OFF;
    float* Ks   = sm + KS_OFF;
    float* Vs   = sm + VS_OFF;
    float* Ps   = sm + PS_OFF;
    float* rsum = sm + RSUM_OFF;

    const int m0 = blockIdx.x * BM;
    const int bz = blockIdx.y;
    const int b  = bz >> 4, h = bz & 15;
    const int tid = threadIdx.x;
    const int warp = tid >> 5, lane = tid & 31;
    const int wm = warp >> 1, wn = warp & 1;
    const int g = lane >> 2, tig = lane & 3;

    const float* __restrict__ A  = latq + (size_t)h * (LL * DH);
    const float* __restrict__ Kg = g_K  + (size_t)bz * TT * DH;
    const float* __restrict__ Vg = g_Vt + (size_t)bz * DH * TT;
    const uint32_t* __restrict__ Mp = g_Mp + (size_t)b * LL * 32;

    const uint32_t ks_u32 = smem_u32(Ks);
    const uint32_t vs_u32 = smem_u32(Vs);

    // stage lq (x0.25, tf32)
    #pragma unroll
    for (int jj = 0; jj < 8; jj++) {
        const int idx = tid + jj * 256;
        const int row = idx >> 4, f4 = idx & 15;
        float4 v = {0.f, 0.f, 0.f, 0.f};
        if (m0 + row < LL) {
            v = *(const float4*)&A[(size_t)(m0 + row) * DH + f4 * 4];
            v.x *= 0.25f; v.y *= 0.25f; v.z *= 0.25f; v.w *= 0.25f;
        }
        float* d = lq_s + row * FSTR + f4 * 4;
        d[0] = f2tf(v.x); d[1] = f2tf(v.y); d[2] = f2tf(v.z); d[3] = f2tf(v.w);
    }

    float co[2][4][4] = {};
    float srow[2][2] = {};
    __syncthreads();

    for (int tile = 0; tile < TT / 64; tile++) {
        const int t0 = tile * 64;
        // stage K tile [t][d] and V tile [d][t] via cp.async (pre-rounded tf32)
        #pragma unroll
        for (int jj = 0; jj < 4; jj++) {
            const int idx = tid + jj * 256;
            const int row = idx >> 4, f4 = idx & 15;
            const uint32_t doff = (uint32_t)(row * FSTR + f4 * 4) * 4u;
            cpa16(ks_u32 + doff, Kg + (size_t)(t0 + row) * DH + f4 * 4);
            cpa16(vs_u32 + doff, Vg + (size_t)row * TT + t0 + f4 * 4);
        }
        asm volatile("cp.async.commit_group;");
        asm volatile("cp.async.wait_group 0;" ::: "memory");
        __syncthreads();

        // S = lq @ K^T
        float cs[2][4][4] = {};
        compute_mma<FSTR, 8>(lq_s, Ks, cs, wm, wn, g, tig);

        // mask words
        uint32_t mw[2][2];
        #pragma unroll
        for (int i = 0; i < 2; i++) {
            const int lA = m0 + wm * 32 + i * 16 + g;
            const int lB = lA + 8;
            mw[i][0] = (lA < LL) ? Mp[(size_t)lA * 32 + tile * 2 + wn] : 0u;
            mw[i][1] = (lB < LL) ? Mp[(size_t)lB * 32 + tile * 2 + wn] : 0u;
        }

        // p = mask ? exp(s) : 0 ; accumulate register row sums ; write P
        #pragma unroll
        for (int i = 0; i < 2; i++) {
            #pragma unroll
            for (int half = 0; half < 2; half++) {
                const int r = wm * 32 + i * 16 + g + half * 8;
                const uint32_t w32 = mw[i][half];
                const int k = half * 2;
                float sl = 0.f;
                #pragma unroll
                for (int j = 0; j < 4; j++) {
                    const int b0 = j * 8 + tig * 2;
                    const float p0 = ((w32 >> b0) & 1)       ? __expf(cs[i][j][k])     : 0.f;
                    const float p1 = ((w32 >> (b0 + 1)) & 1) ? __expf(cs[i][j][k + 1]) : 0.f;
                    sl += p0 + p1;
                    float2 pv = { f2tf(p0), f2tf(p1) };
                    *(float2*)(Ps + r * FSTR + wn * 32 + b0) = pv;
                }
                srow[i][half] += sl;
            }
        }
        __syncthreads();

        // O += P @ V
        compute_mma<FSTR, 8>(Ps, Vs, co, wm, wn, g, tig);
        __syncthreads();
    }

    // final row-sum reduction: tig shfl, then combine the two wn halves via smem
    #pragma unroll
    for (int i = 0; i < 2; i++) {
        #pragma unroll
        for (int half = 0; half < 2; half++) {
            const int r = wm * 32 + i * 16 + g + half * 8;
            float s = srow[i][half];
            s += __shfl_xor_sync(0xffffffffu, s, 1);
            s += __shfl_xor_sync(0xffffffffu, s, 2);
            if (tig == 0) rsum[r * 2 + wn] = s;
        }
    }
    __syncthreads();

    // epilogue: out[b, l, h*64 + d] = O / rowsum  (0 if fully masked)
    #pragma unroll
    for (int i = 0; i < 2; i++) {
        const int rA = wm * 32 + i * 16 + g, rB = rA + 8;
        const int lA = m0 + rA, lB = m0 + rB;
        const float dA = rsum[rA * 2] + rsum[rA * 2 + 1];
        const float dB = rsum[rB * 2] + rsum[rB * 2 + 1];
        const float invA = dA > 0.f ? __frcp_rn(dA) : 0.f;
        const float invB = dB > 0.f ? __frcp_rn(dB) : 0.f;
        #pragma unroll
        for (int j = 0; j < 4; j++) {
            const int nl = wn * 32 + j * 8 + tig * 2;
            if (lA < LL) {
                float2 v0 = { co[i][j][0] * invA, co[i][j][1] * invA };
                *(float2*)(out + ((size_t)b * LL + lA) * DEMB + h * DH + nl) = v0;
            }
            if (lB < LL) {
                float2 v1 = { co[i][j][2] * invB, co[i][j][3] * invB };
                *(float2*)(out + ((size_t)b * LL + lB) * DEMB + h * DH + nl) = v1;
            }
        }
    }
}

// ---------------------------------------------------------------------------
extern "C" void kernel_launch(void* const* d_in, const int* in_sizes, int n_in,
                              void* d_out, int out_size)
{
    const float* x    = (const float*)d_in[0];
    const int*   msk  = (const int*)d_in[1];
    const float* latq = (const float*)d_in[2];
    const float* wk   = (const float*)d_in[3];
    const float* bk   = (const float*)d_in[4];
    const float* wv   = (const float*)d_in[5];
    const float* bv   = (const float*)d_in[6];
    float*       out  = (float*)d_out;

    cudaFuncSetAttribute(proj_kernel, cudaFuncAttributeMaxDynamicSharedMemorySize, SMEMB);
    cudaFuncSetAttribute(attn_fused,  cudaFuncAttributeMaxDynamicSharedMemorySize, SMEM_ATT_B);

    pack_mask<<<BB * LL / 8, 256>>>(msk);
    proj_kernel<<<dim3(32, 16, 2), 256, SMEMB>>>(x, wk, bk, wv, bv);
    attn_fused <<<dim3(11, 64),    256, SMEM_ATT_B>>>(latq, out);
}